// round 8
// baseline (speedup 1.0000x reference)
#include <cuda_runtime.h>
#include <cuda_fp16.h>

#define MAX_NODES 100000

typedef unsigned long long u64;

// fp16 scratch tables: a_n = dw1[0:32]^T z_loop[n] + db1,  b_n = dw1[32:64]^T z_loop[n]
__device__ __half g_ah[MAX_NODES * 64];
__device__ __half g_bh[MAX_NODES * 64];

// ---- packed f32x2 helpers (sm_103a) ----
__device__ __forceinline__ u64 pack2(float lo, float hi) {
    u64 r; asm("mov.b64 %0, {%1, %2};" : "=l"(r) : "f"(lo), "f"(hi)); return r;
}
__device__ __forceinline__ float2 unpack2(u64 v) {
    float2 f; asm("mov.b64 {%0, %1}, %2;" : "=f"(f.x), "=f"(f.y) : "l"(v)); return f;
}
__device__ __forceinline__ u64 fma2(u64 a, u64 b, u64 c) {
    u64 d; asm("fma.rn.f32x2 %0, %1, %2, %3;" : "=l"(d) : "l"(a), "l"(b), "l"(c)); return d;
}

__device__ __forceinline__ void store_half8(__half* p, const float* v)
{
    __align__(16) __half2 h[4];
    h[0] = __floats2half2_rn(v[0], v[1]);
    h[1] = __floats2half2_rn(v[2], v[3]);
    h[2] = __floats2half2_rn(v[4], v[5]);
    h[3] = __floats2half2_rn(v[6], v[7]);
    *reinterpret_cast<uint4*>(p) = *reinterpret_cast<const uint4*>(h);
}

// ---------------------------------------------------------------------------
// Node kernel: f32x2 FMA, 2 nodes/thread. launch_bounds(128, 2) gives a
// 256-reg budget: the ~170 live registers (z0/z1/zl0/zl1 = 128 data regs +
// temps) fit WITHOUT spilling (the R7 (128,3)=170 cap likely spilled).
// ---------------------------------------------------------------------------
__global__ void __launch_bounds__(128, 2)
node_kernel(const float* __restrict__ z_mod,
            const float* __restrict__ w1,   // [32,64]
            const float* __restrict__ b1,   // [64]
            const float* __restrict__ w2,   // [64,32]
            const float* __restrict__ b2,   // [32]
            const float* __restrict__ dw1,  // [64,64]
            const float* __restrict__ db1,  // [64]
            int n_nodes)
{
    __shared__ float s_w1t[64 * 32];   // s_w1t[k*32+c] = w1[c][k]
    __shared__ float s_w2[64 * 32];    // s_w2[k*32+d]  = w2[k][d]
    __shared__ float s_dw1t[64 * 64];  // s_dw1t[k*64+d] = dw1[d][k]
    __shared__ float s_b1[64], s_db1[64], s_b2[32];

    const int t = threadIdx.x;
    for (int idx = t; idx < 64 * 32; idx += 128) {
        int k = idx >> 5, c = idx & 31;
        s_w1t[idx] = w1[c * 64 + k];
        s_w2[idx]  = w2[idx];
    }
    for (int idx = t; idx < 64 * 64; idx += 128) {
        int k = idx >> 6, d = idx & 63;
        s_dw1t[idx] = dw1[d * 64 + k];
    }
    if (t < 64) { s_b1[t] = b1[t]; s_db1[t] = db1[t]; }
    if (t < 32) { s_b2[t] = b2[t]; }
    __syncthreads();

    int n0 = blockIdx.x * 256 + t;
    if (n0 >= n_nodes) return;
    int n1 = n0 + 128;
    if (n1 >= n_nodes) n1 = n_nodes - 1;  // duplicate compute; identical store race benign

    u64 z0[16], z1[16];
    {
        const ulonglong2* zp0 = reinterpret_cast<const ulonglong2*>(z_mod + (size_t)n0 * 32);
        const ulonglong2* zp1 = reinterpret_cast<const ulonglong2*>(z_mod + (size_t)n1 * 32);
#pragma unroll
        for (int c = 0; c < 8; c++) {
            ulonglong2 v0 = zp0[c], v1 = zp1[c];
            z0[2*c] = v0.x; z0[2*c+1] = v0.y;
            z1[2*c] = v1.x; z1[2*c+1] = v1.y;
        }
    }

    u64 zl0[16], zl1[16];
#pragma unroll
    for (int p = 0; p < 16; p++) {
        u64 bp = pack2(s_b2[2*p], s_b2[2*p+1]);
        zl0[p] = bp; zl1[p] = bp;
    }

#pragma unroll 4
    for (int k = 0; k < 64; k++) {
        u64 acc0 = pack2(s_b1[k], 0.0f);
        u64 acc1 = acc0;
        const ulonglong2* wr = reinterpret_cast<const ulonglong2*>(&s_w1t[k * 32]);
#pragma unroll
        for (int c = 0; c < 8; c++) {
            ulonglong2 w = wr[c];
            acc0 = fma2(z0[2*c],   w.x, acc0);
            acc0 = fma2(z0[2*c+1], w.y, acc0);
            acc1 = fma2(z1[2*c],   w.x, acc1);
            acc1 = fma2(z1[2*c+1], w.y, acc1);
        }
        float2 f0 = unpack2(acc0);
        float2 f1 = unpack2(acc1);
        float h0 = fmaxf(f0.x + f0.y, 0.0f);
        float h1 = fmaxf(f1.x + f1.y, 0.0f);
        u64 hb0 = pack2(h0, h0);
        u64 hb1 = pack2(h1, h1);
        const ulonglong2* w2r = reinterpret_cast<const ulonglong2*>(&s_w2[k * 32]);
#pragma unroll
        for (int p = 0; p < 8; p++) {
            ulonglong2 w = w2r[p];
            zl0[2*p]   = fma2(hb0, w.x, zl0[2*p]);
            zl0[2*p+1] = fma2(hb0, w.y, zl0[2*p+1]);
            zl1[2*p]   = fma2(hb1, w.x, zl1[2*p]);
            zl1[2*p+1] = fma2(hb1, w.y, zl1[2*p+1]);
        }
    }

    __half* a0p = g_ah + (size_t)n0 * 64;
    __half* b0p = g_bh + (size_t)n0 * 64;
    __half* a1p = g_ah + (size_t)n1 * 64;
    __half* b1p = g_bh + (size_t)n1 * 64;

#pragma unroll 2
    for (int k8 = 0; k8 < 8; k8++) {
        float a0v[8], b0v[8], a1v[8], b1v[8];
#pragma unroll
        for (int q = 0; q < 8; q++) {
            const int k = k8 * 8 + q;
            u64 A0 = pack2(s_db1[k], 0.0f), A1 = A0;
            u64 B0 = 0ULL, B1 = 0ULL;
            const ulonglong2* wr = reinterpret_cast<const ulonglong2*>(&s_dw1t[k * 64]);
#pragma unroll
            for (int p = 0; p < 8; p++) {
                ulonglong2 w = wr[p];
                A0 = fma2(zl0[2*p],   w.x, A0);
                A0 = fma2(zl0[2*p+1], w.y, A0);
                A1 = fma2(zl1[2*p],   w.x, A1);
                A1 = fma2(zl1[2*p+1], w.y, A1);
            }
#pragma unroll
            for (int p = 0; p < 8; p++) {
                ulonglong2 w = wr[8 + p];
                B0 = fma2(zl0[2*p],   w.x, B0);
                B0 = fma2(zl0[2*p+1], w.y, B0);
                B1 = fma2(zl1[2*p],   w.x, B1);
                B1 = fma2(zl1[2*p+1], w.y, B1);
            }
            float2 fa0 = unpack2(A0), fb0 = unpack2(B0);
            float2 fa1 = unpack2(A1), fb1 = unpack2(B1);
            a0v[q] = fa0.x + fa0.y;  b0v[q] = fb0.x + fb0.y;
            a1v[q] = fa1.x + fa1.y;  b1v[q] = fb1.x + fb1.y;
        }
        store_half8(a0p + k8 * 8, a0v);
        store_half8(b0p + k8 * 8, b0v);
        store_half8(a1p + k8 * 8, a1v);
        store_half8(b1p + k8 * 8, b1v);
    }
}

// ---------------------------------------------------------------------------
// Edge kernel: 8 lanes/edge, subgroup owns 2 consecutive edges (8/warp).
// Lower register footprint (~36) + launch_bounds(256,7) -> occ ~87% to push
// the L1 wavefront unit (the structural bottleneck) toward saturation.
// ---------------------------------------------------------------------------
__device__ __forceinline__ float edge_dot(uint4 ua, uint4 ub,
                                          float4 w0, float4 w1)
{
    const __half2* pa = reinterpret_cast<const __half2*>(&ua);
    const __half2* pb = reinterpret_cast<const __half2*>(&ub);
    const __half2 zero2 = __float2half2_rn(0.0f);
    float2 f0 = __half22float2(__hmax2(__hadd2(pa[0], pb[0]), zero2));
    float2 f1 = __half22float2(__hmax2(__hadd2(pa[1], pb[1]), zero2));
    float2 f2 = __half22float2(__hmax2(__hadd2(pa[2], pb[2]), zero2));
    float2 f3 = __half22float2(__hmax2(__hadd2(pa[3], pb[3]), zero2));
    float acc;
    acc = f0.x * w0.x;
    acc = fmaf(f0.y, w0.y, acc);
    acc = fmaf(f1.x, w0.z, acc);
    acc = fmaf(f1.y, w0.w, acc);
    acc = fmaf(f2.x, w1.x, acc);
    acc = fmaf(f2.y, w1.y, acc);
    acc = fmaf(f3.x, w1.z, acc);
    acc = fmaf(f3.y, w1.w, acc);
    return acc;
}

__global__ void __launch_bounds__(256, 7)
edge_kernel(const int* __restrict__ edge_index,  // [2, E] int32
            const float* __restrict__ dw2,       // [64]
            const float* __restrict__ db2,       // [1]
            float* __restrict__ out, int n_edges)
{
    const int lane = threadIdx.x & 31;
    const int s    = lane >> 3;   // subgroup 0..3
    const int q    = lane & 7;    // lane within subgroup
    const int warp_g = (blockIdx.x * blockDim.x + threadIdx.x) >> 5;
    const int e0 = warp_g * 8 + s * 2;   // 2 consecutive edges per subgroup

    const float4 w0 = __ldg(reinterpret_cast<const float4*>(dw2) + 2 * q);
    const float4 w1 = __ldg(reinterpret_cast<const float4*>(dw2) + 2 * q + 1);
    const float bias = __ldg(db2);
    const uint4* Ab = reinterpret_cast<const uint4*>(g_ah);
    const uint4* Bb = reinterpret_cast<const uint4*>(g_bh);
    const unsigned mask = 0xFFu << (s * 8);

    if (e0 + 2 <= n_edges && (n_edges & 1) == 0) {
        // fast path: vector idx load, no predication, vector store
        const int2 iv = __ldg(reinterpret_cast<const int2*>(edge_index + e0));
        const int2 jv = __ldg(reinterpret_cast<const int2*>(edge_index + n_edges + e0));

        const uint4 ua0 = Ab[(size_t)iv.x * 8 + q];
        const uint4 ub0 = Bb[(size_t)jv.x * 8 + q];
        const uint4 ua1 = Ab[(size_t)iv.y * 8 + q];
        const uint4 ub1 = Bb[(size_t)jv.y * 8 + q];

        float r0 = edge_dot(ua0, ub0, w0, w1);
        float r1 = edge_dot(ua1, ub1, w0, w1);

        r0 += __shfl_xor_sync(mask, r0, 4);
        r1 += __shfl_xor_sync(mask, r1, 4);
        r0 += __shfl_xor_sync(mask, r0, 2);
        r1 += __shfl_xor_sync(mask, r1, 2);
        r0 += __shfl_xor_sync(mask, r0, 1);
        r1 += __shfl_xor_sync(mask, r1, 1);

        if (q == 0) {
            *reinterpret_cast<float2*>(out + e0) =
                make_float2(r0 + bias, r1 + bias);
        }
    } else {
        // tail / unaligned fallback
#pragma unroll
        for (int t = 0; t < 2; t++) {
            const int e = e0 + t;
            const bool live = (e < n_edges);
            int i = 0, j = 0;
            if (live) {
                i = __ldg(edge_index + e);
                j = __ldg(edge_index + n_edges + e);
            }
            uint4 ua = make_uint4(0, 0, 0, 0), ub = make_uint4(0, 0, 0, 0);
            if (live) {
                ua = Ab[(size_t)i * 8 + q];
                ub = Bb[(size_t)j * 8 + q];
            }
            float acc = edge_dot(ua, ub, w0, w1);
            acc += __shfl_xor_sync(mask, acc, 4);
            acc += __shfl_xor_sync(mask, acc, 2);
            acc += __shfl_xor_sync(mask, acc, 1);
            if (live && q == 0) out[e] = acc + bias;
        }
    }
}

// ---------------------------------------------------------------------------
// Launch. Input order (metadata): z_mod, edge_index, w1, b1, w2, b2,
//                                 dw1, db1, dw2, db2
// ---------------------------------------------------------------------------
extern "C" void kernel_launch(void* const* d_in, const int* in_sizes, int n_in,
                              void* d_out, int out_size)
{
    const float* z_mod = (const float*)d_in[0];
    const int*   eidx  = (const int*)d_in[1];
    const float* w1    = (const float*)d_in[2];
    const float* b1    = (const float*)d_in[3];
    const float* w2    = (const float*)d_in[4];
    const float* b2    = (const float*)d_in[5];
    const float* dw1   = (const float*)d_in[6];
    const float* db1   = (const float*)d_in[7];
    const float* dw2   = (const float*)d_in[8];
    const float* db2   = (const float*)d_in[9];
    float* out = (float*)d_out;

    const int n_nodes = in_sizes[0] / 32;
    const int n_edges = in_sizes[1] / 2;

    const int nb_node = (n_nodes + 255) / 256;   // 128 threads, 2 nodes/thread
    node_kernel<<<nb_node, 128>>>(z_mod, w1, b1, w2, b2, dw1, db1, n_nodes);

    const int nb_edge = (n_edges + 63) / 64;     // 8 edges per warp
    edge_kernel<<<nb_edge, 256>>>(eidx, dw2, db2, out, n_edges);
}

// round 9
// speedup vs baseline: 1.0071x; 1.0071x over previous
#include <cuda_runtime.h>
#include <cuda_fp16.h>

#define MAX_NODES 100000

// fp16 scratch tables: a_n = dw1[0:32]^T z_loop[n] + db1,  b_n = dw1[32:64]^T z_loop[n]
// row = 64 halves = 128 bytes = exactly one cache line.
__device__ __half g_ah[MAX_NODES * 64];
__device__ __half g_bh[MAX_NODES * 64];

__device__ __forceinline__ void store_half8(__half* p, const float* v)
{
    __align__(16) __half2 h[4];
    h[0] = __floats2half2_rn(v[0], v[1]);
    h[1] = __floats2half2_rn(v[2], v[3]);
    h[2] = __floats2half2_rn(v[4], v[5]);
    h[3] = __floats2half2_rn(v[6], v[7]);
    *reinterpret_cast<uint4*>(p) = *reinterpret_cast<const uint4*>(h);
}

// ---------------------------------------------------------------------------
// Node kernel (R4 configuration — best measured: ~53.5us).
// TWO nodes per thread, plain fp32 FFMA, weights staged in smem.
// ---------------------------------------------------------------------------
__global__ void __launch_bounds__(256, 1)
node_kernel(const float* __restrict__ z_mod,
            const float* __restrict__ w1,   // [32,64]
            const float* __restrict__ b1,   // [64]
            const float* __restrict__ w2,   // [64,32]
            const float* __restrict__ b2,   // [32]
            const float* __restrict__ dw1,  // [64,64]
            const float* __restrict__ db1,  // [64]
            int n_nodes)
{
    __shared__ float s_w1t[64 * 32];   // s_w1t[k*32+c] = w1[c][k]
    __shared__ float s_w2[64 * 32];    // s_w2[k*32+d]  = w2[k][d]
    __shared__ float s_dw1t[64 * 64];  // s_dw1t[k*64+d] = dw1[d][k]
    __shared__ float s_b1[64], s_db1[64], s_b2[32];

    const int t = threadIdx.x;
    for (int idx = t; idx < 64 * 32; idx += blockDim.x) {
        int k = idx >> 5, c = idx & 31;
        s_w1t[idx] = w1[c * 64 + k];
        s_w2[idx]  = w2[idx];
    }
    for (int idx = t; idx < 64 * 64; idx += blockDim.x) {
        int k = idx >> 6, d = idx & 63;
        s_dw1t[idx] = dw1[d * 64 + k];
    }
    if (t < 64) { s_b1[t] = b1[t]; s_db1[t] = db1[t]; }
    if (t < 32) { s_b2[t] = b2[t]; }
    __syncthreads();

    int n0 = blockIdx.x * 512 + t;
    if (n0 >= n_nodes) return;
    int n1 = n0 + 256;
    if (n1 >= n_nodes) n1 = n_nodes - 1;  // duplicate compute; identical store race benign

    float z0[32], z1[32];
    {
        const float4* zp0 = reinterpret_cast<const float4*>(z_mod + (size_t)n0 * 32);
        const float4* zp1 = reinterpret_cast<const float4*>(z_mod + (size_t)n1 * 32);
#pragma unroll
        for (int c4 = 0; c4 < 8; c4++) {
            float4 v0 = zp0[c4], v1 = zp1[c4];
            z0[c4*4+0] = v0.x; z0[c4*4+1] = v0.y; z0[c4*4+2] = v0.z; z0[c4*4+3] = v0.w;
            z1[c4*4+0] = v1.x; z1[c4*4+1] = v1.y; z1[c4*4+2] = v1.z; z1[c4*4+3] = v1.w;
        }
    }

    float zl0[32], zl1[32];
#pragma unroll
    for (int d = 0; d < 32; d++) { zl0[d] = s_b2[d]; zl1[d] = s_b2[d]; }

#pragma unroll 4
    for (int k = 0; k < 64; k++) {
        float acc0 = s_b1[k], acc1 = s_b1[k];
        const float4* wr = reinterpret_cast<const float4*>(&s_w1t[k * 32]);
#pragma unroll
        for (int c4 = 0; c4 < 8; c4++) {
            float4 w = wr[c4];
            acc0 = fmaf(z0[c4*4+0], w.x, acc0);
            acc0 = fmaf(z0[c4*4+1], w.y, acc0);
            acc0 = fmaf(z0[c4*4+2], w.z, acc0);
            acc0 = fmaf(z0[c4*4+3], w.w, acc0);
            acc1 = fmaf(z1[c4*4+0], w.x, acc1);
            acc1 = fmaf(z1[c4*4+1], w.y, acc1);
            acc1 = fmaf(z1[c4*4+2], w.z, acc1);
            acc1 = fmaf(z1[c4*4+3], w.w, acc1);
        }
        acc0 = fmaxf(acc0, 0.0f);
        acc1 = fmaxf(acc1, 0.0f);
        const float4* w2r = reinterpret_cast<const float4*>(&s_w2[k * 32]);
#pragma unroll
        for (int d4 = 0; d4 < 8; d4++) {
            float4 w = w2r[d4];
            zl0[d4*4+0] = fmaf(acc0, w.x, zl0[d4*4+0]);
            zl0[d4*4+1] = fmaf(acc0, w.y, zl0[d4*4+1]);
            zl0[d4*4+2] = fmaf(acc0, w.z, zl0[d4*4+2]);
            zl0[d4*4+3] = fmaf(acc0, w.w, zl0[d4*4+3]);
            zl1[d4*4+0] = fmaf(acc1, w.x, zl1[d4*4+0]);
            zl1[d4*4+1] = fmaf(acc1, w.y, zl1[d4*4+1]);
            zl1[d4*4+2] = fmaf(acc1, w.z, zl1[d4*4+2]);
            zl1[d4*4+3] = fmaf(acc1, w.w, zl1[d4*4+3]);
        }
    }

    __half* a0p = g_ah + (size_t)n0 * 64;
    __half* b0p = g_bh + (size_t)n0 * 64;
    __half* a1p = g_ah + (size_t)n1 * 64;
    __half* b1p = g_bh + (size_t)n1 * 64;

#pragma unroll 2
    for (int k8 = 0; k8 < 8; k8++) {
        float a0v[8], b0v[8], a1v[8], b1v[8];
#pragma unroll
        for (int q = 0; q < 8; q++) {
            const int k = k8 * 8 + q;
            float A0 = s_db1[k], B0 = 0.0f, A1 = s_db1[k], B1 = 0.0f;
            const float4* wr = reinterpret_cast<const float4*>(&s_dw1t[k * 64]);
#pragma unroll
            for (int d4 = 0; d4 < 8; d4++) {
                float4 w = wr[d4];
                A0 = fmaf(zl0[d4*4+0], w.x, A0);
                A0 = fmaf(zl0[d4*4+1], w.y, A0);
                A0 = fmaf(zl0[d4*4+2], w.z, A0);
                A0 = fmaf(zl0[d4*4+3], w.w, A0);
                A1 = fmaf(zl1[d4*4+0], w.x, A1);
                A1 = fmaf(zl1[d4*4+1], w.y, A1);
                A1 = fmaf(zl1[d4*4+2], w.z, A1);
                A1 = fmaf(zl1[d4*4+3], w.w, A1);
            }
#pragma unroll
            for (int d4 = 0; d4 < 8; d4++) {
                float4 w = wr[8 + d4];
                B0 = fmaf(zl0[d4*4+0], w.x, B0);
                B0 = fmaf(zl0[d4*4+1], w.y, B0);
                B0 = fmaf(zl0[d4*4+2], w.z, B0);
                B0 = fmaf(zl0[d4*4+3], w.w, B0);
                B1 = fmaf(zl1[d4*4+0], w.x, B1);
                B1 = fmaf(zl1[d4*4+1], w.y, B1);
                B1 = fmaf(zl1[d4*4+2], w.z, B1);
                B1 = fmaf(zl1[d4*4+3], w.w, B1);
            }
            a0v[q] = A0; b0v[q] = B0; a1v[q] = A1; b1v[q] = B1;
        }
        store_half8(a0p + k8 * 8, a0v);
        store_half8(b0p + k8 * 8, b0v);
        store_half8(a1p + k8 * 8, a1v);
        store_half8(b1p + k8 * 8, b1v);
    }
}

// ---------------------------------------------------------------------------
// Edge kernel (R6 configuration — best measured: 67.4us).
// 8 lanes/edge, subgroup owns 4 consecutive edges: int4 idx loads,
// 8 front-batched gathers, zero hot-path predication, one STG.128.
// ---------------------------------------------------------------------------
__device__ __forceinline__ float edge_dot(uint4 ua, uint4 ub,
                                          float4 w0, float4 w1)
{
    const __half2* pa = reinterpret_cast<const __half2*>(&ua);
    const __half2* pb = reinterpret_cast<const __half2*>(&ub);
    const __half2 zero2 = __float2half2_rn(0.0f);
    float2 f0 = __half22float2(__hmax2(__hadd2(pa[0], pb[0]), zero2));
    float2 f1 = __half22float2(__hmax2(__hadd2(pa[1], pb[1]), zero2));
    float2 f2 = __half22float2(__hmax2(__hadd2(pa[2], pb[2]), zero2));
    float2 f3 = __half22float2(__hmax2(__hadd2(pa[3], pb[3]), zero2));
    float acc;
    acc = f0.x * w0.x;
    acc = fmaf(f0.y, w0.y, acc);
    acc = fmaf(f1.x, w0.z, acc);
    acc = fmaf(f1.y, w0.w, acc);
    acc = fmaf(f2.x, w1.x, acc);
    acc = fmaf(f2.y, w1.y, acc);
    acc = fmaf(f3.x, w1.z, acc);
    acc = fmaf(f3.y, w1.w, acc);
    return acc;
}

__global__ void __launch_bounds__(256)
edge_kernel(const int* __restrict__ edge_index,  // [2, E] int32
            const float* __restrict__ dw2,       // [64]
            const float* __restrict__ db2,       // [1]
            float* __restrict__ out, int n_edges)
{
    const int lane = threadIdx.x & 31;
    const int s    = lane >> 3;   // subgroup 0..3
    const int q    = lane & 7;    // lane within subgroup
    const int warp_g = (blockIdx.x * blockDim.x + threadIdx.x) >> 5;
    const int e0 = warp_g * 16 + s * 4;   // 4 consecutive edges per subgroup

    const float4 w0 = __ldg(reinterpret_cast<const float4*>(dw2) + 2 * q);
    const float4 w1 = __ldg(reinterpret_cast<const float4*>(dw2) + 2 * q + 1);
    const float bias = __ldg(db2);
    const uint4* Ab = reinterpret_cast<const uint4*>(g_ah);
    const uint4* Bb = reinterpret_cast<const uint4*>(g_bh);
    const unsigned mask = 0xFFu << (s * 8);

    if (e0 + 4 <= n_edges && (n_edges & 3) == 0) {
        // ---- fast path: no predication ----
        const int4 iv = __ldg(reinterpret_cast<const int4*>(edge_index + e0));
        const int4 jv = __ldg(reinterpret_cast<const int4*>(edge_index + n_edges + e0));

        const uint4 ua0 = Ab[(size_t)iv.x * 8 + q];
        const uint4 ub0 = Bb[(size_t)jv.x * 8 + q];
        const uint4 ua1 = Ab[(size_t)iv.y * 8 + q];
        const uint4 ub1 = Bb[(size_t)jv.y * 8 + q];
        const uint4 ua2 = Ab[(size_t)iv.z * 8 + q];
        const uint4 ub2 = Bb[(size_t)jv.z * 8 + q];
        const uint4 ua3 = Ab[(size_t)iv.w * 8 + q];
        const uint4 ub3 = Bb[(size_t)jv.w * 8 + q];

        float r0 = edge_dot(ua0, ub0, w0, w1);
        float r1 = edge_dot(ua1, ub1, w0, w1);
        float r2 = edge_dot(ua2, ub2, w0, w1);
        float r3 = edge_dot(ua3, ub3, w0, w1);

        r0 += __shfl_xor_sync(mask, r0, 4);
        r1 += __shfl_xor_sync(mask, r1, 4);
        r2 += __shfl_xor_sync(mask, r2, 4);
        r3 += __shfl_xor_sync(mask, r3, 4);
        r0 += __shfl_xor_sync(mask, r0, 2);
        r1 += __shfl_xor_sync(mask, r1, 2);
        r2 += __shfl_xor_sync(mask, r2, 2);
        r3 += __shfl_xor_sync(mask, r3, 2);
        r0 += __shfl_xor_sync(mask, r0, 1);
        r1 += __shfl_xor_sync(mask, r1, 1);
        r2 += __shfl_xor_sync(mask, r2, 1);
        r3 += __shfl_xor_sync(mask, r3, 1);

        if (q == 0) {
            *reinterpret_cast<float4*>(out + e0) =
                make_float4(r0 + bias, r1 + bias, r2 + bias, r3 + bias);
        }
    } else {
        // ---- tail / unaligned fallback ----
#pragma unroll
        for (int t = 0; t < 4; t++) {
            const int e = e0 + t;
            const bool live = (e < n_edges);
            int i = 0, j = 0;
            if (live) {
                i = __ldg(edge_index + e);
                j = __ldg(edge_index + n_edges + e);
            }
            uint4 ua = make_uint4(0, 0, 0, 0), ub = make_uint4(0, 0, 0, 0);
            if (live) {
                ua = Ab[(size_t)i * 8 + q];
                ub = Bb[(size_t)j * 8 + q];
            }
            float acc = edge_dot(ua, ub, w0, w1);
            acc += __shfl_xor_sync(mask, acc, 4);
            acc += __shfl_xor_sync(mask, acc, 2);
            acc += __shfl_xor_sync(mask, acc, 1);
            if (live && q == 0) out[e] = acc + bias;
        }
    }
}

// ---------------------------------------------------------------------------
// Launch. Input order (metadata): z_mod, edge_index, w1, b1, w2, b2,
//                                 dw1, db1, dw2, db2
// ---------------------------------------------------------------------------
extern "C" void kernel_launch(void* const* d_in, const int* in_sizes, int n_in,
                              void* d_out, int out_size)
{
    const float* z_mod = (const float*)d_in[0];
    const int*   eidx  = (const int*)d_in[1];
    const float* w1    = (const float*)d_in[2];
    const float* b1    = (const float*)d_in[3];
    const float* w2    = (const float*)d_in[4];
    const float* b2    = (const float*)d_in[5];
    const float* dw1   = (const float*)d_in[6];
    const float* db1   = (const float*)d_in[7];
    const float* dw2   = (const float*)d_in[8];
    const float* db2   = (const float*)d_in[9];
    float* out = (float*)d_out;

    const int n_nodes = in_sizes[0] / 32;
    const int n_edges = in_sizes[1] / 2;

    const int nb_node = (n_nodes + 511) / 512;   // 256 threads, 2 nodes/thread
    node_kernel<<<nb_node, 256>>>(z_mod, w1, b1, w2, b2, dw1, db1, n_nodes);

    const int nb_edge = (n_edges + 127) / 128;   // 16 edges per warp
    edge_kernel<<<nb_edge, 256>>>(eidx, dw2, db2, out, n_edges);
}

// round 11
// speedup vs baseline: 1.0896x; 1.0819x over previous
#include <cuda_runtime.h>
#include <cuda_fp16.h>

#define MAX_NODES 100000

typedef unsigned long long u64;

// fp16 scratch tables: a_n = dw1[0:32]^T z_loop[n] + db1,  b_n = dw1[32:64]^T z_loop[n]
// row = 64 halves = 128 bytes = exactly one cache line.
__device__ __half g_ah[MAX_NODES * 64];
__device__ __half g_bh[MAX_NODES * 64];

// ---- packed f32x2 helpers (sm_103a) ----
__device__ __forceinline__ u64 pack2(float lo, float hi) {
    u64 r; asm("mov.b64 %0, {%1, %2};" : "=l"(r) : "f"(lo), "f"(hi)); return r;
}
__device__ __forceinline__ float2 unpack2(u64 v) {
    float2 f; asm("mov.b64 {%0, %1}, %2;" : "=f"(f.x), "=f"(f.y) : "l"(v)); return f;
}
__device__ __forceinline__ u64 fma2(u64 a, u64 b, u64 c) {
    u64 d; asm("fma.rn.f32x2 %0, %1, %2, %3;" : "=l"(d) : "l"(a), "l"(b), "l"(c)); return d;
}

__device__ __forceinline__ void store_half8(__half* p, const float* v)
{
    __align__(16) __half2 h[4];
    h[0] = __floats2half2_rn(v[0], v[1]);
    h[1] = __floats2half2_rn(v[2], v[3]);
    h[2] = __floats2half2_rn(v[4], v[5]);
    h[3] = __floats2half2_rn(v[6], v[7]);
    *reinterpret_cast<uint4*>(p) = *reinterpret_cast<const uint4*>(h);
}

// ---------------------------------------------------------------------------
// Node kernel (R8 configuration — best measured: ~55.9us).
// f32x2 FMA, 2 nodes/thread, launch_bounds(128, 2) (no spills).
// ---------------------------------------------------------------------------
__global__ void __launch_bounds__(128, 2)
node_kernel(const float* __restrict__ z_mod,
            const float* __restrict__ w1,   // [32,64]
            const float* __restrict__ b1,   // [64]
            const float* __restrict__ w2,   // [64,32]
            const float* __restrict__ b2,   // [32]
            const float* __restrict__ dw1,  // [64,64]
            const float* __restrict__ db1,  // [64]
            int n_nodes)
{
    __shared__ float s_w1t[64 * 32];   // s_w1t[k*32+c] = w1[c][k]
    __shared__ float s_w2[64 * 32];    // s_w2[k*32+d]  = w2[k][d]
    __shared__ float s_dw1t[64 * 64];  // s_dw1t[k*64+d] = dw1[d][k]
    __shared__ float s_b1[64], s_db1[64], s_b2[32];

    const int t = threadIdx.x;
    for (int idx = t; idx < 64 * 32; idx += 128) {
        int k = idx >> 5, c = idx & 31;
        s_w1t[idx] = w1[c * 64 + k];
        s_w2[idx]  = w2[idx];
    }
    for (int idx = t; idx < 64 * 64; idx += 128) {
        int k = idx >> 6, d = idx & 63;
        s_dw1t[idx] = dw1[d * 64 + k];
    }
    if (t < 64) { s_b1[t] = b1[t]; s_db1[t] = db1[t]; }
    if (t < 32) { s_b2[t] = b2[t]; }
    __syncthreads();

    int n0 = blockIdx.x * 256 + t;
    if (n0 >= n_nodes) return;
    int n1 = n0 + 128;
    if (n1 >= n_nodes) n1 = n_nodes - 1;  // duplicate compute; identical store race benign

    u64 z0[16], z1[16];
    {
        const ulonglong2* zp0 = reinterpret_cast<const ulonglong2*>(z_mod + (size_t)n0 * 32);
        const ulonglong2* zp1 = reinterpret_cast<const ulonglong2*>(z_mod + (size_t)n1 * 32);
#pragma unroll
        for (int c = 0; c < 8; c++) {
            ulonglong2 v0 = zp0[c], v1 = zp1[c];
            z0[2*c] = v0.x; z0[2*c+1] = v0.y;
            z1[2*c] = v1.x; z1[2*c+1] = v1.y;
        }
    }

    u64 zl0[16], zl1[16];
#pragma unroll
    for (int p = 0; p < 16; p++) {
        u64 bp = pack2(s_b2[2*p], s_b2[2*p+1]);
        zl0[p] = bp; zl1[p] = bp;
    }

#pragma unroll 4
    for (int k = 0; k < 64; k++) {
        u64 acc0 = pack2(s_b1[k], 0.0f);
        u64 acc1 = acc0;
        const ulonglong2* wr = reinterpret_cast<const ulonglong2*>(&s_w1t[k * 32]);
#pragma unroll
        for (int c = 0; c < 8; c++) {
            ulonglong2 w = wr[c];
            acc0 = fma2(z0[2*c],   w.x, acc0);
            acc0 = fma2(z0[2*c+1], w.y, acc0);
            acc1 = fma2(z1[2*c],   w.x, acc1);
            acc1 = fma2(z1[2*c+1], w.y, acc1);
        }
        float2 f0 = unpack2(acc0);
        float2 f1 = unpack2(acc1);
        float h0 = fmaxf(f0.x + f0.y, 0.0f);
        float h1 = fmaxf(f1.x + f1.y, 0.0f);
        u64 hb0 = pack2(h0, h0);
        u64 hb1 = pack2(h1, h1);
        const ulonglong2* w2r = reinterpret_cast<const ulonglong2*>(&s_w2[k * 32]);
#pragma unroll
        for (int p = 0; p < 8; p++) {
            ulonglong2 w = w2r[p];
            zl0[2*p]   = fma2(hb0, w.x, zl0[2*p]);
            zl0[2*p+1] = fma2(hb0, w.y, zl0[2*p+1]);
            zl1[2*p]   = fma2(hb1, w.x, zl1[2*p]);
            zl1[2*p+1] = fma2(hb1, w.y, zl1[2*p+1]);
        }
    }

    __half* a0p = g_ah + (size_t)n0 * 64;
    __half* b0p = g_bh + (size_t)n0 * 64;
    __half* a1p = g_ah + (size_t)n1 * 64;
    __half* b1p = g_bh + (size_t)n1 * 64;

#pragma unroll 2
    for (int k8 = 0; k8 < 8; k8++) {
        float a0v[8], b0v[8], a1v[8], b1v[8];
#pragma unroll
        for (int q = 0; q < 8; q++) {
            const int k = k8 * 8 + q;
            u64 A0 = pack2(s_db1[k], 0.0f), A1 = A0;
            u64 B0 = 0ULL, B1 = 0ULL;
            const ulonglong2* wr = reinterpret_cast<const ulonglong2*>(&s_dw1t[k * 64]);
#pragma unroll
            for (int p = 0; p < 8; p++) {
                ulonglong2 w = wr[p];
                A0 = fma2(zl0[2*p],   w.x, A0);
                A0 = fma2(zl0[2*p+1], w.y, A0);
                A1 = fma2(zl1[2*p],   w.x, A1);
                A1 = fma2(zl1[2*p+1], w.y, A1);
            }
#pragma unroll
            for (int p = 0; p < 8; p++) {
                ulonglong2 w = wr[8 + p];
                B0 = fma2(zl0[2*p],   w.x, B0);
                B0 = fma2(zl0[2*p+1], w.y, B0);
                B1 = fma2(zl1[2*p],   w.x, B1);
                B1 = fma2(zl1[2*p+1], w.y, B1);
            }
            float2 fa0 = unpack2(A0), fb0 = unpack2(B0);
            float2 fa1 = unpack2(A1), fb1 = unpack2(B1);
            a0v[q] = fa0.x + fa0.y;  b0v[q] = fb0.x + fb0.y;
            a1v[q] = fa1.x + fa1.y;  b1v[q] = fb1.x + fb1.y;
        }
        store_half8(a0p + k8 * 8, a0v);
        store_half8(b0p + k8 * 8, b0v);
        store_half8(a1p + k8 * 8, a1v);
        store_half8(b1p + k8 * 8, b1v);
    }
}

// ---------------------------------------------------------------------------
// Edge kernel (R6 configuration — best measured: 67.4us).
// 8 lanes/edge, subgroup owns 4 consecutive edges: int4 idx loads,
// 8 front-batched gathers, zero hot-path predication, one STG.128.
// ---------------------------------------------------------------------------
__device__ __forceinline__ float edge_dot(uint4 ua, uint4 ub,
                                          float4 w0, float4 w1)
{
    const __half2* pa = reinterpret_cast<const __half2*>(&ua);
    const __half2* pb = reinterpret_cast<const __half2*>(&ub);
    const __half2 zero2 = __float2half2_rn(0.0f);
    float2 f0 = __half22float2(__hmax2(__hadd2(pa[0], pb[0]), zero2));
    float2 f1 = __half22float2(__hmax2(__hadd2(pa[1], pb[1]), zero2));
    float2 f2 = __half22float2(__hmax2(__hadd2(pa[2], pb[2]), zero2));
    float2 f3 = __half22float2(__hmax2(__hadd2(pa[3], pb[3]), zero2));
    float acc;
    acc = f0.x * w0.x;
    acc = fmaf(f0.y, w0.y, acc);
    acc = fmaf(f1.x, w0.z, acc);
    acc = fmaf(f1.y, w0.w, acc);
    acc = fmaf(f2.x, w1.x, acc);
    acc = fmaf(f2.y, w1.y, acc);
    acc = fmaf(f3.x, w1.z, acc);
    acc = fmaf(f3.y, w1.w, acc);
    return acc;
}

__global__ void __launch_bounds__(256)
edge_kernel(const int* __restrict__ edge_index,  // [2, E] int32
            const float* __restrict__ dw2,       // [64]
            const float* __restrict__ db2,       // [1]
            float* __restrict__ out, int n_edges)
{
    const int lane = threadIdx.x & 31;
    const int s    = lane >> 3;   // subgroup 0..3
    const int q    = lane & 7;    // lane within subgroup
    const int warp_g = (blockIdx.x * blockDim.x + threadIdx.x) >> 5;
    const int e0 = warp_g * 16 + s * 4;   // 4 consecutive edges per subgroup

    const float4 w0 = __ldg(reinterpret_cast<const float4*>(dw2) + 2 * q);
    const float4 w1 = __ldg(reinterpret_cast<const float4*>(dw2) + 2 * q + 1);
    const float bias = __ldg(db2);
    const uint4* Ab = reinterpret_cast<const uint4*>(g_ah);
    const uint4* Bb = reinterpret_cast<const uint4*>(g_bh);
    const unsigned mask = 0xFFu << (s * 8);

    if (e0 + 4 <= n_edges && (n_edges & 3) == 0) {
        // ---- fast path: no predication ----
        const int4 iv = __ldg(reinterpret_cast<const int4*>(edge_index + e0));
        const int4 jv = __ldg(reinterpret_cast<const int4*>(edge_index + n_edges + e0));

        const uint4 ua0 = Ab[(size_t)iv.x * 8 + q];
        const uint4 ub0 = Bb[(size_t)jv.x * 8 + q];
        const uint4 ua1 = Ab[(size_t)iv.y * 8 + q];
        const uint4 ub1 = Bb[(size_t)jv.y * 8 + q];
        const uint4 ua2 = Ab[(size_t)iv.z * 8 + q];
        const uint4 ub2 = Bb[(size_t)jv.z * 8 + q];
        const uint4 ua3 = Ab[(size_t)iv.w * 8 + q];
        const uint4 ub3 = Bb[(size_t)jv.w * 8 + q];

        float r0 = edge_dot(ua0, ub0, w0, w1);
        float r1 = edge_dot(ua1, ub1, w0, w1);
        float r2 = edge_dot(ua2, ub2, w0, w1);
        float r3 = edge_dot(ua3, ub3, w0, w1);

        r0 += __shfl_xor_sync(mask, r0, 4);
        r1 += __shfl_xor_sync(mask, r1, 4);
        r2 += __shfl_xor_sync(mask, r2, 4);
        r3 += __shfl_xor_sync(mask, r3, 4);
        r0 += __shfl_xor_sync(mask, r0, 2);
        r1 += __shfl_xor_sync(mask, r1, 2);
        r2 += __shfl_xor_sync(mask, r2, 2);
        r3 += __shfl_xor_sync(mask, r3, 2);
        r0 += __shfl_xor_sync(mask, r0, 1);
        r1 += __shfl_xor_sync(mask, r1, 1);
        r2 += __shfl_xor_sync(mask, r2, 1);
        r3 += __shfl_xor_sync(mask, r3, 1);

        if (q == 0) {
            *reinterpret_cast<float4*>(out + e0) =
                make_float4(r0 + bias, r1 + bias, r2 + bias, r3 + bias);
        }
    } else {
        // ---- tail / unaligned fallback ----
#pragma unroll
        for (int t = 0; t < 4; t++) {
            const int e = e0 + t;
            const bool live = (e < n_edges);
            int i = 0, j = 0;
            if (live) {
                i = __ldg(edge_index + e);
                j = __ldg(edge_index + n_edges + e);
            }
            uint4 ua = make_uint4(0, 0, 0, 0), ub = make_uint4(0, 0, 0, 0);
            if (live) {
                ua = Ab[(size_t)i * 8 + q];
                ub = Bb[(size_t)j * 8 + q];
            }
            float acc = edge_dot(ua, ub, w0, w1);
            acc += __shfl_xor_sync(mask, acc, 4);
            acc += __shfl_xor_sync(mask, acc, 2);
            acc += __shfl_xor_sync(mask, acc, 1);
            if (live && q == 0) out[e] = acc + bias;
        }
    }
}

// ---------------------------------------------------------------------------
// Launch. Input order (metadata): z_mod, edge_index, w1, b1, w2, b2,
//                                 dw1, db1, dw2, db2
// ---------------------------------------------------------------------------
extern "C" void kernel_launch(void* const* d_in, const int* in_sizes, int n_in,
                              void* d_out, int out_size)
{
    const float* z_mod = (const float*)d_in[0];
    const int*   eidx  = (const int*)d_in[1];
    const float* w1    = (const float*)d_in[2];
    const float* b1    = (const float*)d_in[3];
    const float* w2    = (const float*)d_in[4];
    const float* b2    = (const float*)d_in[5];
    const float* dw1   = (const float*)d_in[6];
    const float* db1   = (const float*)d_in[7];
    const float* dw2   = (const float*)d_in[8];
    const float* db2   = (const float*)d_in[9];
    float* out = (float*)d_out;

    const int n_nodes = in_sizes[0] / 32;
    const int n_edges = in_sizes[1] / 2;

    const int nb_node = (n_nodes + 255) / 256;   // 128 threads, 2 nodes/thread
    node_kernel<<<nb_node, 128>>>(z_mod, w1, b1, w2, b2, dw1, db1, n_nodes);

    const int nb_edge = (n_edges + 127) / 128;   // 16 edges per warp
    edge_kernel<<<nb_edge, 256>>>(eidx, dw2, db2, out, n_edges);
}